// round 15
// baseline (speedup 1.0000x reference)
#include <cuda_runtime.h>
#include <cuda.h>
#include <cstdint>

#define BDIM 288
#define DISP 4
#define ND 9
#define CH 128
#define HH 96
#define WW 160
#define NB 8
#define TY 8
#define TX 32
#define CCH 8
#define NBUF 2
#define NSTAGE (CH / CCH)        // 16
// Padded strides via TMA box (box0 = smem row pitch)
#define SRS 44
#define SROWS 16
#define SCS (SROWS * SRS)        // 704 floats / channel
#define FRS 36
#define FROWS 8
#define FCS (FROWS * FRS)        // 288 floats / channel
#define SBUF_FL (CCH * SCS)      // 5632 floats per S buffer
#define FBUF_FL (CCH * FCS)      // 2304 floats per F buffer
#define SBYTES (SBUF_FL * 4)     // 22528 (128B aligned)
#define FBYTES (FBUF_FL * 4)     // 9216  (128B aligned)
#define STAGE_BYTES (SBYTES + FBYTES)    // 31744
#define SMEM_S_OFF 0
#define SMEM_F_OFF (NBUF * SBYTES)                 // 45056
#define SMEM_MBAR_OFF (SMEM_F_OFF + NBUF * FBYTES) // 63488
#define SMEM_TOTAL (SMEM_MBAR_OFF + NBUF * 8)      // 63504

typedef unsigned long long u64;
typedef unsigned int u32;

struct F2 { float lo, hi; };

static __device__ __forceinline__ u64 pk(float lo, float hi) {
    u64 r; asm("mov.b64 %0, {%1, %2};" : "=l"(r) : "f"(lo), "f"(hi)); return r;
}
static __device__ __forceinline__ F2 unp(u64 v) {
    F2 r; asm("mov.b64 {%0, %1}, %2;" : "=f"(r.lo), "=f"(r.hi) : "l"(v)); return r;
}
static __device__ __forceinline__ void fma2(u64 &d, u64 a, u64 b) {
    asm("fma.rn.f32x2 %0, %1, %2, %0;" : "+l"(d) : "l"(a), "l"(b));
}

#define MBAR_INIT(addr, cnt) \
    asm volatile("mbarrier.init.shared.b64 [%0], %1;" :: "r"(addr), "r"(cnt) : "memory")
#define MBAR_EXPECT_TX(addr, bytes) \
    asm volatile("mbarrier.arrive.expect_tx.shared.b64 _, [%0], %1;" :: "r"(addr), "r"(bytes) : "memory")
#define TMA_LD3D(smem, tmap, cx, cy, cz, mbar) \
    asm volatile("cp.async.bulk.tensor.3d.shared::cta.global.tile.mbarrier::complete_tx::bytes " \
                 "[%0], [%1, {%2, %3, %4}], [%5];" \
                 :: "r"(smem), "l"(tmap), "r"(cx), "r"(cy), "r"(cz), "r"(mbar) : "memory")

static __device__ __forceinline__ void mbar_wait(u32 addr, u32 phase) {
    asm volatile(
        "{\n\t"
        ".reg .pred P1;\n\t"
        "WAIT_LOOP_%=:\n\t"
        "mbarrier.try_wait.parity.acquire.cta.shared::cta.b64 P1, [%0], %1, 0x989680;\n\t"
        "@P1 bra.uni WAIT_DONE_%=;\n\t"
        "bra.uni WAIT_LOOP_%=;\n\t"
        "WAIT_DONE_%=:\n\t"
        "}"
        :: "r"(addr), "r"(phase) : "memory");
}

__global__ __launch_bounds__(BDIM, 2)
void corr_kernel(const float* __restrict__ first,
                 const float* __restrict__ second,
                 float* __restrict__ out,
                 const __grid_constant__ CUtensorMap tmF,
                 const __grid_constant__ CUtensorMap tmS) {
    extern __shared__ __align__(1024) char smem[];
    float* sSbuf = (float*)(smem + SMEM_S_OFF);
    float* sFbuf = (float*)(smem + SMEM_F_OFF);

    const int tid = threadIdx.x;
    const int b   = blockIdx.z;
    const int y0  = blockIdx.y * TY;
    const int x0  = blockIdx.x * TX;

    const int d    = tid >> 5;      // dy 0..8
    const int lane = tid & 31;
    const int ty   = lane >> 2;     // 0..7
    const int xg   = lane & 3;      // 0..3

    const u32 base = (u32)__cvta_generic_to_shared(smem);
    const u32 sS0 = base + SMEM_S_OFF;
    const u32 sF0 = base + SMEM_F_OFF;
    const u32 mb0 = base + SMEM_MBAR_OFF;

    if (tid == 0) {
        MBAR_INIT(mb0 + 0, 1);
        MBAR_INIT(mb0 + 8, 1);
    }
    __syncthreads();

    const int zbase = b * CH;

    auto issue = [&](int s, int bi) {
        if (tid == 0) {
            const u32 mb = mb0 + bi * 8;
            MBAR_EXPECT_TX(mb, STAGE_BYTES);
            const int z = zbase + s * CCH;
            TMA_LD3D(sS0 + bi * SBYTES, &tmS, x0 - DISP, y0 - DISP, z, mb);
            TMA_LD3D(sF0 + bi * FBYTES, &tmF, x0,        y0,        z, mb);
        }
    };

    u64 acc[36];
    #pragma unroll
    for (int i = 0; i < 36; i++) acc[i] = 0ull;

    auto compute = [&](int bi) {   // bi compile-time
        const float* fptr = &sFbuf[bi * FBUF_FL + ty * FRS + 8 * xg];
        const float* sptr = &sSbuf[bi * SBUF_FL + (ty + d) * SRS + 8 * xg];

        // Two compile-time register banks; loads for channel cc+1 issue
        // before the fma block of channel cc. No cross-bank copies.
        ulonglong2 Ea[2][4];
        ulonglong2 Fa[2][2];

        Fa[0][0] = *reinterpret_cast<const ulonglong2*>(fptr);
        Fa[0][1] = *reinterpret_cast<const ulonglong2*>(fptr + 4);
        Ea[0][0] = *reinterpret_cast<const ulonglong2*>(sptr);
        Ea[0][1] = *reinterpret_cast<const ulonglong2*>(sptr + 4);
        Ea[0][2] = *reinterpret_cast<const ulonglong2*>(sptr + 8);
        Ea[0][3] = *reinterpret_cast<const ulonglong2*>(sptr + 12);

        #pragma unroll
        for (int cc = 0; cc < CCH; cc++) {
            const int cur = cc & 1;
            const int nxt = cur ^ 1;
            if (cc + 1 < CCH) {
                const float* fp = fptr + (cc + 1) * FCS;
                const float* sp = sptr + (cc + 1) * SCS;
                Fa[nxt][0] = *reinterpret_cast<const ulonglong2*>(fp);
                Fa[nxt][1] = *reinterpret_cast<const ulonglong2*>(fp + 4);
                Ea[nxt][0] = *reinterpret_cast<const ulonglong2*>(sp);
                Ea[nxt][1] = *reinterpret_cast<const ulonglong2*>(sp + 4);
                Ea[nxt][2] = *reinterpret_cast<const ulonglong2*>(sp + 8);
                Ea[nxt][3] = *reinterpret_cast<const ulonglong2*>(sp + 12);
            }

            const F2 a0 = unp(Ea[cur][0].x), a1 = unp(Ea[cur][0].y);
            const F2 a2 = unp(Ea[cur][1].x), a3 = unp(Ea[cur][1].y);
            const F2 a4 = unp(Ea[cur][2].x), a5 = unp(Ea[cur][2].y);
            const F2 a6 = unp(Ea[cur][3].x), a7 = unp(Ea[cur][3].y);

            u64 P[15];
            P[0]  = Ea[cur][0].x;     P[2]  = Ea[cur][0].y;
            P[4]  = Ea[cur][1].x;     P[6]  = Ea[cur][1].y;
            P[8]  = Ea[cur][2].x;     P[10] = Ea[cur][2].y;
            P[12] = Ea[cur][3].x;     P[14] = Ea[cur][3].y;
            P[1]  = pk(a0.hi, a1.lo); P[3]  = pk(a1.hi, a2.lo);
            P[5]  = pk(a2.hi, a3.lo); P[7]  = pk(a3.hi, a4.lo);
            P[9]  = pk(a4.hi, a5.lo); P[11] = pk(a5.hi, a6.lo);
            P[13] = pk(a6.hi, a7.lo);

            const u64 f0 = Fa[cur][0].x, f1 = Fa[cur][0].y;
            const u64 f2 = Fa[cur][1].x, f3 = Fa[cur][1].y;

            #pragma unroll
            for (int j = 0; j < ND; j++) {
                fma2(acc[j],      f0, P[j]);
                fma2(acc[9 + j],  f1, P[2 + j]);
                fma2(acc[18 + j], f2, P[4 + j]);
                fma2(acc[27 + j], f3, P[6 + j]);
            }
        }
    };

    auto body = [&](int s, int bi, u32 ph) {
        mbar_wait(mb0 + bi * 8, ph);
        compute(bi);
        __syncthreads();
        if (s + NBUF < NSTAGE) issue(s + NBUF, bi);
    };

    issue(0, 0);
    issue(1, 1);

    #pragma unroll 1
    for (int t = 0; t < 8; t++) {
        const u32 ph = (u32)(t & 1);
        body(2 * t + 0, 0, ph);
        body(2 * t + 1, 1, ph);
    }

    // ---- epilogue: chan = dy*9 + dx (dx fastest) ----
    const float inv_c = 1.0f / (float)CH;
    const int gy = y0 + ty;
    const int gx = x0 + 8 * xg;
    char* outB = (char*)out;
    u32 obase = (u32)((((b * 81 + d * ND) * HH + gy) * WW + gx) * 4);
    #pragma unroll
    for (int j = 0; j < ND; j++) {
        float* o = (float*)(outB + obase);
        obase += (u32)(HH * WW * 4);
        const F2 r0 = unp(acc[j]);
        const F2 r1 = unp(acc[9 + j]);
        const F2 r2 = unp(acc[18 + j]);
        const F2 r3 = unp(acc[27 + j]);
        float4 v0 = make_float4(r0.lo * inv_c, r0.hi * inv_c, r1.lo * inv_c, r1.hi * inv_c);
        float4 v1 = make_float4(r2.lo * inv_c, r2.hi * inv_c, r3.lo * inv_c, r3.hi * inv_c);
        *reinterpret_cast<float4*>(o)     = v0;
        *reinterpret_cast<float4*>(o + 4) = v1;
    }
}

// ---------------- host side ----------------

typedef CUresult (*EncodeTiledFn)(
    CUtensorMap*, CUtensorMapDataType, cuuint32_t, void*,
    const cuuint64_t*, const cuuint64_t*, const cuuint32_t*, const cuuint32_t*,
    CUtensorMapInterleave, CUtensorMapSwizzle, CUtensorMapL2promotion,
    CUtensorMapFloatOOBfill);

static void encode_map(EncodeTiledFn enc, CUtensorMap* tm, const void* base,
                       uint32_t bx, uint32_t by) {
    cuuint64_t dims[3]    = { WW, HH, (cuuint64_t)NB * CH };
    cuuint64_t strides[2] = { WW * 4ull, (cuuint64_t)WW * HH * 4ull };
    cuuint32_t box[3]     = { bx, by, CCH };
    cuuint32_t estr[3]    = { 1, 1, 1 };
    enc(tm, CU_TENSOR_MAP_DATA_TYPE_FLOAT32, 3, const_cast<void*>(base),
        dims, strides, box, estr,
        CU_TENSOR_MAP_INTERLEAVE_NONE, CU_TENSOR_MAP_SWIZZLE_NONE,
        CU_TENSOR_MAP_L2_PROMOTION_L2_128B, CU_TENSOR_MAP_FLOAT_OOB_FILL_NONE);
}

extern "C" void kernel_launch(void* const* d_in, const int* in_sizes, int n_in,
                              void* d_out, int out_size) {
    const float* first  = (const float*)d_in[0];
    const float* second = (const float*)d_in[1];
    float* out = (float*)d_out;
    (void)in_sizes; (void)n_in; (void)out_size;

    void* fp = nullptr;
    cudaDriverEntryPointQueryResult qr;
    cudaGetDriverEntryPointByVersion("cuTensorMapEncodeTiled", &fp, 12000,
                                     cudaEnableDefault, &qr);
    EncodeTiledFn enc = (EncodeTiledFn)fp;

    CUtensorMap tmF, tmS;
    encode_map(enc, &tmF, first,  FRS, FROWS);   // box 36 x 8  x 8 -> pitch 36
    encode_map(enc, &tmS, second, SRS, SROWS);   // box 44 x 16 x 8 -> pitch 44

    cudaFuncSetAttribute(corr_kernel,
                         cudaFuncAttributeMaxDynamicSharedMemorySize, SMEM_TOTAL);

    dim3 grid(WW / TX, HH / TY, NB);   // (5, 12, 8)
    corr_kernel<<<grid, BDIM, SMEM_TOTAL>>>(first, second, out, tmF, tmS);
}

// round 17
// speedup vs baseline: 1.3856x; 1.3856x over previous
#include <cuda_runtime.h>
#include <cuda.h>
#include <cstdint>

#define BDIM 256
#define DISP 4
#define ND 9
#define CH 128
#define HH 96
#define WW 160
#define NB 8
#define TY 8
#define TX 32
#define CCH 8
#define NBUF 2
#define NSTAGE (CH / CCH)        // 16
// Padded strides via TMA box (box0 = smem row pitch)
#define SRS 44
#define SROWS 16
#define SCS (SROWS * SRS)        // 704 floats / channel
#define FRS 36
#define FROWS 8
#define FCS (FROWS * FRS)        // 288 floats / channel
#define SBUF_FL (CCH * SCS)      // 5632 floats per S buffer
#define FBUF_FL (CCH * FCS)      // 2304 floats per F buffer
#define SBYTES (SBUF_FL * 4)     // 22528 (128B aligned)
#define FBYTES (FBUF_FL * 4)     // 9216  (128B aligned)
#define STAGE_BYTES (SBYTES + FBYTES)    // 31744
#define SMEM_S_OFF 0
#define SMEM_F_OFF (NBUF * SBYTES)                 // 45056
#define SMEM_MBAR_OFF (SMEM_F_OFF + NBUF * FBYTES) // 63488
#define SMEM_TOTAL (SMEM_MBAR_OFF + NBUF * 8)      // 63504

typedef unsigned long long u64;
typedef unsigned int u32;

struct F2 { float lo, hi; };

static __device__ __forceinline__ u64 pk(float lo, float hi) {
    u64 r; asm("mov.b64 %0, {%1, %2};" : "=l"(r) : "f"(lo), "f"(hi)); return r;
}
static __device__ __forceinline__ F2 unp(u64 v) {
    F2 r; asm("mov.b64 {%0, %1}, %2;" : "=f"(r.lo), "=f"(r.hi) : "l"(v)); return r;
}
static __device__ __forceinline__ void fma2(u64 &d, u64 a, u64 b) {
    asm("fma.rn.f32x2 %0, %1, %2, %0;" : "+l"(d) : "l"(a), "l"(b));
}

#define MBAR_INIT(addr, cnt) \
    asm volatile("mbarrier.init.shared.b64 [%0], %1;" :: "r"(addr), "r"(cnt) : "memory")
#define MBAR_EXPECT_TX(addr, bytes) \
    asm volatile("mbarrier.arrive.expect_tx.shared.b64 _, [%0], %1;" :: "r"(addr), "r"(bytes) : "memory")
#define TMA_LD3D(smem, tmap, cx, cy, cz, mbar) \
    asm volatile("cp.async.bulk.tensor.3d.shared::cta.global.tile.mbarrier::complete_tx::bytes " \
                 "[%0], [%1, {%2, %3, %4}], [%5];" \
                 :: "r"(smem), "l"(tmap), "r"(cx), "r"(cy), "r"(cz), "r"(mbar) : "memory")

static __device__ __forceinline__ void mbar_wait(u32 addr, u32 phase) {
    asm volatile(
        "{\n\t"
        ".reg .pred P1;\n\t"
        "WAIT_LOOP_%=:\n\t"
        "mbarrier.try_wait.parity.acquire.cta.shared::cta.b64 P1, [%0], %1, 0x989680;\n\t"
        "@P1 bra.uni WAIT_DONE_%=;\n\t"
        "bra.uni WAIT_LOOP_%=;\n\t"
        "WAIT_DONE_%=:\n\t"
        "}"
        :: "r"(addr), "r"(phase) : "memory");
}

__global__ __launch_bounds__(BDIM, 2)
void corr_kernel(const float* __restrict__ first,
                 const float* __restrict__ second,
                 float* __restrict__ out,
                 const __grid_constant__ CUtensorMap tmF,
                 const __grid_constant__ CUtensorMap tmS) {
    extern __shared__ __align__(1024) char smem[];
    float* sSbuf = (float*)(smem + SMEM_S_OFF);
    float* sFbuf = (float*)(smem + SMEM_F_OFF);

    const int tid = threadIdx.x;
    const int b   = blockIdx.z;
    const int y0  = blockIdx.y * TY;
    const int x0  = blockIdx.x * TX;

    const int d    = tid >> 5;      // warp id = dy 0..7 (dy=8 handled by all)
    const int lane = tid & 31;
    const int ty   = lane >> 2;     // 0..7
    const int xg   = lane & 3;      // 0..3

    const u32 base = (u32)__cvta_generic_to_shared(smem);
    const u32 sS0 = base + SMEM_S_OFF;
    const u32 sF0 = base + SMEM_F_OFF;
    const u32 mb0 = base + SMEM_MBAR_OFF;

    if (tid == 0) {
        MBAR_INIT(mb0 + 0, 1);
        MBAR_INIT(mb0 + 8, 1);
    }
    __syncthreads();

    const int zbase = b * CH;

    auto issue = [&](int s, int bi) {
        if (tid == 0) {
            const u32 mb = mb0 + bi * 8;
            MBAR_EXPECT_TX(mb, STAGE_BYTES);
            const int z = zbase + s * CCH;
            TMA_LD3D(sS0 + bi * SBYTES, &tmS, x0 - DISP, y0 - DISP, z, mb);
            TMA_LD3D(sF0 + bi * FBYTES, &tmF, x0,        y0,        z, mb);
        }
    };

    u64 acc[36];                 // dy=d part: [pixel-pair][dx]
    #pragma unroll
    for (int i = 0; i < 36; i++) acc[i] = 0ull;
    float acc9[ND];              // dy=8 part: pixel (row d, col lane), 9 dx
    #pragma unroll
    for (int j = 0; j < ND; j++) acc9[j] = 0.0f;

    auto compute = [&](int bi) {   // bi compile-time
        const float* fptr  = &sFbuf[bi * FBUF_FL + ty * FRS + 8 * xg];
        const float* sptr  = &sSbuf[bi * SBUF_FL + (ty + d) * SRS + 8 * xg];
        const float* f2ptr = &sFbuf[bi * FBUF_FL + d * FRS + lane];       // dy=8 F
        const float* s2ptr = &sSbuf[bi * SBUF_FL + (d + 8) * SRS + lane]; // dy=8 E
        #pragma unroll
        for (int cc = 0; cc < CCH; cc++) {
            const ulonglong2 F01 = *reinterpret_cast<const ulonglong2*>(fptr + cc * FCS);
            const ulonglong2 F23 = *reinterpret_cast<const ulonglong2*>(fptr + cc * FCS + 4);
            const ulonglong2 E01 = *reinterpret_cast<const ulonglong2*>(sptr + cc * SCS);
            const ulonglong2 E23 = *reinterpret_cast<const ulonglong2*>(sptr + cc * SCS + 4);
            const ulonglong2 E45 = *reinterpret_cast<const ulonglong2*>(sptr + cc * SCS + 8);
            const ulonglong2 E67 = *reinterpret_cast<const ulonglong2*>(sptr + cc * SCS + 12);

            const F2 a0 = unp(E01.x), a1 = unp(E01.y);
            const F2 a2 = unp(E23.x), a3 = unp(E23.y);
            const F2 a4 = unp(E45.x), a5 = unp(E45.y);
            const F2 a6 = unp(E67.x), a7 = unp(E67.y);

            u64 P[15];
            P[0]  = E01.x;            P[2]  = E01.y;
            P[4]  = E23.x;            P[6]  = E23.y;
            P[8]  = E45.x;            P[10] = E45.y;
            P[12] = E67.x;            P[14] = E67.y;
            P[1]  = pk(a0.hi, a1.lo); P[3]  = pk(a1.hi, a2.lo);
            P[5]  = pk(a2.hi, a3.lo); P[7]  = pk(a3.hi, a4.lo);
            P[9]  = pk(a4.hi, a5.lo); P[11] = pk(a5.hi, a6.lo);
            P[13] = pk(a6.hi, a7.lo);

            #pragma unroll
            for (int j = 0; j < ND; j++) {
                fma2(acc[j],      F01.x, P[j]);
                fma2(acc[9 + j],  F01.y, P[2 + j]);
                fma2(acc[18 + j], F23.x, P[4 + j]);
                fma2(acc[27 + j], F23.y, P[6 + j]);
            }

            // dy=8 scalar part: 1 px per thread, conflict-free scalar LDS
            const float fv = f2ptr[cc * FCS];
            #pragma unroll
            for (int j = 0; j < ND; j++)
                acc9[j] = fmaf(fv, s2ptr[cc * SCS + j], acc9[j]);
        }
    };

    auto body = [&](int s, int bi, u32 ph) {
        mbar_wait(mb0 + bi * 8, ph);
        compute(bi);
        __syncthreads();
        if (s + NBUF < NSTAGE) issue(s + NBUF, bi);
    };

    issue(0, 0);
    issue(1, 1);

    #pragma unroll 1
    for (int t = 0; t < 8; t++) {
        const u32 ph = (u32)(t & 1);
        body(2 * t + 0, 0, ph);
        body(2 * t + 1, 1, ph);
    }

    // ---- epilogue: chan = dy*9 + dx (dx fastest) ----
    const float inv_c = 1.0f / (float)CH;
    char* outB = (char*)out;
    {
        const int gy = y0 + ty;
        const int gx = x0 + 8 * xg;
        u32 obase = (u32)((((b * 81 + d * ND) * HH + gy) * WW + gx) * 4);
        #pragma unroll
        for (int j = 0; j < ND; j++) {
            float* o = (float*)(outB + obase);
            obase += (u32)(HH * WW * 4);
            const F2 r0 = unp(acc[j]);
            const F2 r1 = unp(acc[9 + j]);
            const F2 r2 = unp(acc[18 + j]);
            const F2 r3 = unp(acc[27 + j]);
            float4 v0 = make_float4(r0.lo * inv_c, r0.hi * inv_c, r1.lo * inv_c, r1.hi * inv_c);
            float4 v1 = make_float4(r2.lo * inv_c, r2.hi * inv_c, r3.lo * inv_c, r3.hi * inv_c);
            *reinterpret_cast<float4*>(o)     = v0;
            *reinterpret_cast<float4*>(o + 4) = v1;
        }
    }
    {   // dy=8 channels 72..80: thread (d, lane) -> pixel (y0+d, x0+lane)
        const int gy = y0 + d;
        const int gx = x0 + lane;
        u32 obase = (u32)((((b * 81 + 72) * HH + gy) * WW + gx) * 4);
        #pragma unroll
        for (int j = 0; j < ND; j++) {
            *(float*)(outB + obase) = acc9[j] * inv_c;
            obase += (u32)(HH * WW * 4);
        }
    }
}

// ---------------- host side ----------------

typedef CUresult (*EncodeTiledFn)(
    CUtensorMap*, CUtensorMapDataType, cuuint32_t, void*,
    const cuuint64_t*, const cuuint64_t*, const cuuint32_t*, const cuuint32_t*,
    CUtensorMapInterleave, CUtensorMapSwizzle, CUtensorMapL2promotion,
    CUtensorMapFloatOOBfill);

static void encode_map(EncodeTiledFn enc, CUtensorMap* tm, const void* base,
                       uint32_t bx, uint32_t by) {
    cuuint64_t dims[3]    = { WW, HH, (cuuint64_t)NB * CH };
    cuuint64_t strides[2] = { WW * 4ull, (cuuint64_t)WW * HH * 4ull };
    cuuint32_t box[3]     = { bx, by, CCH };
    cuuint32_t estr[3]    = { 1, 1, 1 };
    enc(tm, CU_TENSOR_MAP_DATA_TYPE_FLOAT32, 3, const_cast<void*>(base),
        dims, strides, box, estr,
        CU_TENSOR_MAP_INTERLEAVE_NONE, CU_TENSOR_MAP_SWIZZLE_NONE,
        CU_TENSOR_MAP_L2_PROMOTION_L2_128B, CU_TENSOR_MAP_FLOAT_OOB_FILL_NONE);
}

extern "C" void kernel_launch(void* const* d_in, const int* in_sizes, int n_in,
                              void* d_out, int out_size) {
    const float* first  = (const float*)d_in[0];
    const float* second = (const float*)d_in[1];
    float* out = (float*)d_out;
    (void)in_sizes; (void)n_in; (void)out_size;

    void* fp = nullptr;
    cudaDriverEntryPointQueryResult qr;
    cudaGetDriverEntryPointByVersion("cuTensorMapEncodeTiled", &fp, 12000,
                                     cudaEnableDefault, &qr);
    EncodeTiledFn enc = (EncodeTiledFn)fp;

    CUtensorMap tmF, tmS;
    encode_map(enc, &tmF, first,  FRS, FROWS);   // box 36 x 8  x 8 -> pitch 36
    encode_map(enc, &tmS, second, SRS, SROWS);   // box 44 x 16 x 8 -> pitch 44

    cudaFuncSetAttribute(corr_kernel,
                         cudaFuncAttributeMaxDynamicSharedMemorySize, SMEM_TOTAL);

    dim3 grid(WW / TX, HH / TY, NB);   // (5, 12, 8)
    corr_kernel<<<grid, BDIM, SMEM_TOTAL>>>(first, second, out, tmF, tmS);
}